// round 3
// baseline (speedup 1.0000x reference)
#include <cuda_runtime.h>

#define EPSF 1e-5f

namespace {
constexpr int NBLK = 1024;
constexpr int THREADS = 256;
constexpr int CTXP = 68;           // ctx row pitch (16B aligned, bank-shift 4/row)
constexpr int WP   = 68;           // staged-weight row pitch
constexpr int RP   = 68;           // bufA row pitch
constexpr int BP   = 68;           // bufB row pitch
constexpr int HS   = 64 * RP + 4;  // bufA head stride (4356; mod32=4 -> distinct banks per head)

constexpr int OFF_CTX = 0;                      // 256*68 = 17408
constexpr int OFF_W   = OFF_CTX + 256 * CTXP;   // 4*64*68 = 17408
constexpr int OFF_A   = OFF_W + 4 * 64 * WP;    // 4*HS = 17424 (QK/AGG, feats staging, OBUF)
constexpr int OFF_B   = OFF_A + 4 * HS;         // 64*68 = 4352 (QP / OA)
constexpr int OFF_AB  = OFF_B + 64 * BP;        // 1024 (softmax weights)
constexpr int SMEM_FLOATS = OFF_AB + 1024;      // 57616 floats = 230464 B
}

__device__ __forceinline__ float warp_sum(float v) {
#pragma unroll
    for (int o = 16; o; o >>= 1) v += __shfl_xor_sync(0xffffffffu, v, o);
    return v;
}
__device__ __forceinline__ void fma4(float4& a, float s, float4 w) {
    a.x = fmaf(s, w.x, a.x); a.y = fmaf(s, w.y, a.y);
    a.z = fmaf(s, w.z, a.z); a.w = fmaf(s, w.w, a.w);
}
__device__ __forceinline__ float dot4(float4 a, float4 b) {
    return fmaf(a.x, b.x, fmaf(a.y, b.y, fmaf(a.z, b.z, a.w * b.w)));
}
__device__ __forceinline__ const float4* f4p(const float* p) {
    return reinterpret_cast<const float4*>(p);
}

__global__ __launch_bounds__(THREADS, 1)
void cma_fused(const float* __restrict__ feats, const float* __restrict__ proj_w,
               const float* __restrict__ proj_b, const float* __restrict__ wq,
               const float* __restrict__ wk, const float* __restrict__ wv,
               const float* __restrict__ bq, const float* __restrict__ bk,
               const float* __restrict__ bv, const float* __restrict__ wo,
               const float* __restrict__ bo, const float* __restrict__ ng,
               const float* __restrict__ nb, const float* __restrict__ tfw,
               const float* __restrict__ fg, const float* __restrict__ fb,
               float* __restrict__ out)
{
    (void)bk;  // cancels in the k'-softmax (adds a per-(n,h) constant to scores)

    extern __shared__ float sm[];
    float* sctx = sm + OFF_CTX;
    float* swgt = sm + OFF_W;
    float* bufA = sm + OFF_A;
    float* bufB = sm + OFF_B;
    float* abuf = sm + OFF_AB;

    const int b    = blockIdx.x;
    const int tid  = threadIdx.x;
    const int lane = tid & 31;
    const int warp = tid >> 5;
    const int tr   = tid >> 4;   // 0..15
    const int tc   = tid & 15;   // 0..15
    const int r0   = tr * 4;
    const int c0   = tc * 4;

    float wgt[4];
    {
        float t0 = __ldg(tfw + 0), t1 = __ldg(tfw + 1), t2 = __ldg(tfw + 2), t3 = __ldg(tfw + 3);
        float tm = fmaxf(fmaxf(t0, t1), fmaxf(t2, t3));
        float e0 = __expf(t0 - tm), e1 = __expf(t1 - tm), e2 = __expf(t2 - tm), e3 = __expf(t3 - tm);
        float inv = 1.f / (e0 + e1 + e2 + e3);
        wgt[0] = e0 * inv; wgt[1] = e1 * inv; wgt[2] = e2 * inv; wgt[3] = e3 * inv;
    }

    // ================= Phase 1: proj -> sctx[(k*64+d)*CTXP + t] =================
    {
        float*  sfeat = bufA;                       // [c][t] pitch 64
        float4* sf4   = reinterpret_cast<float4*>(sfeat);
        float*  spw   = swgt;                       // [c*WP + d]
        for (int k = 0; k < 4; k++) {
            const float4* fgl = f4p(feats + (size_t)(k * NBLK + b) * (128 * 64));
#pragma unroll
            for (int idx = tid; idx < 2048; idx += THREADS) sf4[idx] = fgl[idx];
            const float* pwg = proj_w + k * 8192;
#pragma unroll
            for (int idx = tid; idx < 8192; idx += THREADS) {
                int d = idx >> 7, c = idx & 127;
                spw[c * WP + d] = pwg[idx];
            }
            __syncthreads();

            float4 acc[4] = {{0,0,0,0},{0,0,0,0},{0,0,0,0},{0,0,0,0}};
#pragma unroll 8
            for (int c = 0; c < 128; c++) {
                float4 f = sf4[c * 16 + tc];
                float4 w = *f4p(spw + c * WP + r0);
                fma4(acc[0], w.x, f); fma4(acc[1], w.y, f);
                fma4(acc[2], w.z, f); fma4(acc[3], w.w, f);
            }
#pragma unroll
            for (int j = 0; j < 4; j++) {
                float pb = __ldg(proj_b + k * 64 + r0 + j);
                float4 o = acc[j];
                o.x += pb; o.y += pb; o.z += pb; o.w += pb;
                *reinterpret_cast<float4*>(&sctx[(k * 64 + r0 + j) * CTXP + c0]) = o;
            }
            __syncthreads();
        }
    }

    // ================= Phase 2: per-model attention =================
    for (int i = 0; i < 4; i++) {
        {   // stage transposed weights: s[t*WP+e] = w[e*64+t]
            const float* gq = wq + i * 4096; const float* gk = wk + i * 4096;
            const float* gv = wv + i * 4096; const float* go = wo + i * 4096;
#pragma unroll
            for (int idx = tid; idx < 4096; idx += THREADS) {
                int e = idx >> 6, t = idx & 63;
                swgt[0 * 64 * WP + t * WP + e] = gq[idx];
                swgt[1 * 64 * WP + t * WP + e] = gk[idx];
                swgt[2 * 64 * WP + t * WP + e] = gv[idx];
                swgt[3 * 64 * WP + t * WP + e] = go[idx];
            }
        }
        __syncthreads();
        const float* swq_ = swgt;
        const float* swk_ = swgt + 64 * WP;
        const float* swv_ = swgt + 2 * 64 * WP;
        const float* swo_ = swgt + 3 * 64 * WP;

        int jb_[4];
#pragma unroll
        for (int rr = 0; rr < 4; rr++) {
            int r = r0 + rr;
            jb_[rr] = ((r >> 4) << 6) + ((r & 15) << 2);
        }

        // ---- G1: QP[r][e] = bq[e] + q_in[r] @ wq^T  -> bufB ----
        {
            float4 acc[4] = {{0,0,0,0},{0,0,0,0},{0,0,0,0},{0,0,0,0}};
            const float* q0b = sctx + (jb_[0] + i) * CTXP;
            const float* q1b = sctx + (jb_[1] + i) * CTXP;
            const float* q2b = sctx + (jb_[2] + i) * CTXP;
            const float* q3b = sctx + (jb_[3] + i) * CTXP;
#pragma unroll 4
            for (int t0 = 0; t0 < 64; t0 += 4) {
                float4 q0 = *f4p(q0b + t0), q1 = *f4p(q1b + t0);
                float4 q2 = *f4p(q2b + t0), q3 = *f4p(q3b + t0);
                float4 w0 = *f4p(swq_ + (t0 + 0) * WP + c0);
                float4 w1 = *f4p(swq_ + (t0 + 1) * WP + c0);
                float4 w2 = *f4p(swq_ + (t0 + 2) * WP + c0);
                float4 w3 = *f4p(swq_ + (t0 + 3) * WP + c0);
                fma4(acc[0], q0.x, w0); fma4(acc[0], q0.y, w1); fma4(acc[0], q0.z, w2); fma4(acc[0], q0.w, w3);
                fma4(acc[1], q1.x, w0); fma4(acc[1], q1.y, w1); fma4(acc[1], q1.z, w2); fma4(acc[1], q1.w, w3);
                fma4(acc[2], q2.x, w0); fma4(acc[2], q2.y, w1); fma4(acc[2], q2.z, w2); fma4(acc[2], q2.w, w3);
                fma4(acc[3], q3.x, w0); fma4(acc[3], q3.y, w1); fma4(acc[3], q3.z, w2); fma4(acc[3], q3.w, w3);
            }
            float4 bq4 = *f4p(bq + i * 64 + c0);
#pragma unroll
            for (int rr = 0; rr < 4; rr++) {
                float4 o = acc[rr];
                o.x += bq4.x; o.y += bq4.y; o.z += bq4.z; o.w += bq4.w;
                *reinterpret_cast<float4*>(&bufB[(r0 + rr) * BP + c0]) = o;
            }
        }
        __syncthreads();

        // ---- G2: QK[h][r][t] = 0.25 * sum_{e in h} QP[r][e]*wk[e][t], cols t = tc+16j ----
#pragma unroll
        for (int h = 0; h < 4; h++) {
            float acc[4][4] = {};
#pragma unroll
            for (int e0 = h * 16; e0 < h * 16 + 16; e0 += 4) {
                float4 p0 = *f4p(bufB + (r0 + 0) * BP + e0);
                float4 p1 = *f4p(bufB + (r0 + 1) * BP + e0);
                float4 p2 = *f4p(bufB + (r0 + 2) * BP + e0);
                float4 p3 = *f4p(bufB + (r0 + 3) * BP + e0);
                float4 k0 = *f4p(swk_ + (tc +  0) * WP + e0);
                float4 k1 = *f4p(swk_ + (tc + 16) * WP + e0);
                float4 k2 = *f4p(swk_ + (tc + 32) * WP + e0);
                float4 k3 = *f4p(swk_ + (tc + 48) * WP + e0);
                acc[0][0] += dot4(p0, k0); acc[0][1] += dot4(p0, k1); acc[0][2] += dot4(p0, k2); acc[0][3] += dot4(p0, k3);
                acc[1][0] += dot4(p1, k0); acc[1][1] += dot4(p1, k1); acc[1][2] += dot4(p1, k2); acc[1][3] += dot4(p1, k3);
                acc[2][0] += dot4(p2, k0); acc[2][1] += dot4(p2, k1); acc[2][2] += dot4(p2, k2); acc[2][3] += dot4(p2, k3);
                acc[3][0] += dot4(p3, k0); acc[3][1] += dot4(p3, k1); acc[3][2] += dot4(p3, k2); acc[3][3] += dot4(p3, k3);
            }
#pragma unroll
            for (int rr = 0; rr < 4; rr++)
#pragma unroll
                for (int j = 0; j < 4; j++)
                    bufA[h * HS + (r0 + rr) * RP + tc + 16 * j] = acc[rr][j] * 0.25f;
        }
        __syncthreads();

        // ---- G3a: scores + softmax over k' -> abuf[r*16 + h*4 + kp] ----
#pragma unroll
        for (int p = 0; p < 4; p++) {
            int r   = warp * 8 + p * 2 + (lane >> 4);
            int sub = lane & 15;
            int h   = sub >> 2, kp = sub & 3;
            int j   = ((r >> 4) << 6) + ((r & 15) << 2) + kp;
            const float* qr = bufA + h * HS + r * RP;
            const float* cr = sctx + j * CTXP;
            float s = 0.f;
#pragma unroll
            for (int t0 = 0; t0 < 64; t0 += 4) s += dot4(*f4p(qr + t0), *f4p(cr + t0));
            float m = fmaxf(s, __shfl_xor_sync(0xffffffffu, s, 1));
            m = fmaxf(m, __shfl_xor_sync(0xffffffffu, m, 2));
            float pe  = __expf(s - m);
            float den = pe + __shfl_xor_sync(0xffffffffu, pe, 1);
            den += __shfl_xor_sync(0xffffffffu, den, 2);
            abuf[r * 16 + sub] = pe / den;
        }
        __syncthreads();

        // ---- G3b: AGG[h][r][t] = sum_kp a * ctx (overwrites QK) ----
#pragma unroll
        for (int h = 0; h < 4; h++) {
            float4 acc[4] = {{0,0,0,0},{0,0,0,0},{0,0,0,0},{0,0,0,0}};
#pragma unroll
            for (int rr = 0; rr < 4; rr++) {
                float4 a4 = *f4p(abuf + (r0 + rr) * 16 + h * 4);
                fma4(acc[rr], a4.x, *f4p(sctx + (jb_[rr] + 0) * CTXP + c0));
                fma4(acc[rr], a4.y, *f4p(sctx + (jb_[rr] + 1) * CTXP + c0));
                fma4(acc[rr], a4.z, *f4p(sctx + (jb_[rr] + 2) * CTXP + c0));
                fma4(acc[rr], a4.w, *f4p(sctx + (jb_[rr] + 3) * CTXP + c0));
            }
#pragma unroll
            for (int rr = 0; rr < 4; rr++)
                *reinterpret_cast<float4*>(&bufA[h * HS + (r0 + rr) * RP + c0]) = acc[rr];
        }
        __syncthreads();

        // ---- G4: OA[r][e] = bv[e] + sum_t AGG[h(e)][r][t]*wv[e][t] -> bufB ----
        {
            const float* gb = bufA + (c0 >> 4) * HS;
            float4 acc[4] = {{0,0,0,0},{0,0,0,0},{0,0,0,0},{0,0,0,0}};
#pragma unroll 4
            for (int t0 = 0; t0 < 64; t0 += 4) {
                float4 g0 = *f4p(gb + (r0 + 0) * RP + t0);
                float4 g1 = *f4p(gb + (r0 + 1) * RP + t0);
                float4 g2 = *f4p(gb + (r0 + 2) * RP + t0);
                float4 g3 = *f4p(gb + (r0 + 3) * RP + t0);
                float4 w0 = *f4p(swv_ + (t0 + 0) * WP + c0);
                float4 w1 = *f4p(swv_ + (t0 + 1) * WP + c0);
                float4 w2 = *f4p(swv_ + (t0 + 2) * WP + c0);
                float4 w3 = *f4p(swv_ + (t0 + 3) * WP + c0);
                fma4(acc[0], g0.x, w0); fma4(acc[0], g0.y, w1); fma4(acc[0], g0.z, w2); fma4(acc[0], g0.w, w3);
                fma4(acc[1], g1.x, w0); fma4(acc[1], g1.y, w1); fma4(acc[1], g1.z, w2); fma4(acc[1], g1.w, w3);
                fma4(acc[2], g2.x, w0); fma4(acc[2], g2.y, w1); fma4(acc[2], g2.z, w2); fma4(acc[2], g2.w, w3);
                fma4(acc[3], g3.x, w0); fma4(acc[3], g3.y, w1); fma4(acc[3], g3.z, w2); fma4(acc[3], g3.w, w3);
            }
            float4 bv4 = *f4p(bv + i * 64 + c0);
#pragma unroll
            for (int rr = 0; rr < 4; rr++) {
                float4 o = acc[rr];
                o.x += bv4.x; o.y += bv4.y; o.z += bv4.z; o.w += bv4.w;
                *reinterpret_cast<float4*>(&bufB[(r0 + rr) * BP + c0]) = o;
            }
        }
        __syncthreads();

        // ---- G5: O[r][e'] = bo + OA @ wo^T -> bufA (pitch RP) ----
        {
            float4 acc[4] = {{0,0,0,0},{0,0,0,0},{0,0,0,0},{0,0,0,0}};
#pragma unroll 4
            for (int e0 = 0; e0 < 64; e0 += 4) {
                float4 v0 = *f4p(bufB + (r0 + 0) * BP + e0);
                float4 v1 = *f4p(bufB + (r0 + 1) * BP + e0);
                float4 v2 = *f4p(bufB + (r0 + 2) * BP + e0);
                float4 v3 = *f4p(bufB + (r0 + 3) * BP + e0);
                float4 w0 = *f4p(swo_ + (e0 + 0) * WP + c0);
                float4 w1 = *f4p(swo_ + (e0 + 1) * WP + c0);
                float4 w2 = *f4p(swo_ + (e0 + 2) * WP + c0);
                float4 w3 = *f4p(swo_ + (e0 + 3) * WP + c0);
                fma4(acc[0], v0.x, w0); fma4(acc[0], v0.y, w1); fma4(acc[0], v0.z, w2); fma4(acc[0], v0.w, w3);
                fma4(acc[1], v1.x, w0); fma4(acc[1], v1.y, w1); fma4(acc[1], v1.z, w2); fma4(acc[1], v1.w, w3);
                fma4(acc[2], v2.x, w0); fma4(acc[2], v2.y, w1); fma4(acc[2], v2.z, w2); fma4(acc[2], v2.w, w3);
                fma4(acc[3], v3.x, w0); fma4(acc[3], v3.y, w1); fma4(acc[3], v3.z, w2); fma4(acc[3], v3.w, w3);
            }
            float4 bo4 = *f4p(bo + i * 64 + c0);
#pragma unroll
            for (int rr = 0; rr < 4; rr++) {
                float4 o = acc[rr];
                o.x += bo4.x; o.y += bo4.y; o.z += bo4.z; o.w += bo4.w;
                *reinterpret_cast<float4*>(&bufA[(r0 + rr) * RP + c0]) = o;
            }
        }
        __syncthreads();

        // ---- LN over 64 (+residual q_in), scale by wgt[i], stage into out ----
#pragma unroll
        for (int p = 0; p < 8; p++) {
            int r   = warp * 8 + p;
            int jqr = ((r >> 4) << 6) + ((r & 15) << 2) + i;
            float x0 = bufA[r * RP + lane]      + sctx[jqr * CTXP + lane];
            float x1 = bufA[r * RP + lane + 32] + sctx[jqr * CTXP + lane + 32];
            float mean = warp_sum(x0 + x1) * (1.f / 64.f);
            float d0 = x0 - mean, d1 = x1 - mean;
            float var = warp_sum(d0 * d0 + d1 * d1) * (1.f / 64.f);
            float rs = rsqrtf(var + EPSF);
            float* dst = out + ((size_t)b * 16384 + r * 256 + i * 64);
            dst[lane]      = (d0 * rs * __ldg(ng + i * 64 + lane)      + __ldg(nb + i * 64 + lane))      * wgt[i];
            dst[lane + 32] = (d1 * rs * __ldg(ng + i * 64 + lane + 32) + __ldg(nb + i * 64 + lane + 32)) * wgt[i];
        }
        __syncthreads();
    }

    // ================= Phase 3: final LN over 256, in-place on out (float4) =================
    const float4* fg4 = f4p(fg);
    const float4* fb4 = f4p(fb);
#pragma unroll
    for (int p = 0; p < 8; p++) {
        int r = warp * 8 + p;
        float4* row4 = reinterpret_cast<float4*>(out + (size_t)b * 16384 + r * 256);
        float4 xa = row4[lane], xb = row4[lane + 32];
        float s = xa.x + xa.y + xa.z + xa.w + xb.x + xb.y + xb.z + xb.w;
        float mean = warp_sum(s) * (1.f / 256.f);
        xa.x -= mean; xa.y -= mean; xa.z -= mean; xa.w -= mean;
        xb.x -= mean; xb.y -= mean; xb.z -= mean; xb.w -= mean;
        float v = xa.x*xa.x + xa.y*xa.y + xa.z*xa.z + xa.w*xa.w
                + xb.x*xb.x + xb.y*xb.y + xb.z*xb.z + xb.w*xb.w;
        float var = warp_sum(v) * (1.f / 256.f);
        float rs = rsqrtf(var + EPSF);
        float4 ga = fg4[lane], gb = fg4[lane + 32];
        float4 ba = fb4[lane], bb = fb4[lane + 32];
        row4[lane]      = make_float4(fmaf(xa.x * rs, ga.x, ba.x), fmaf(xa.y * rs, ga.y, ba.y),
                                      fmaf(xa.z * rs, ga.z, ba.z), fmaf(xa.w * rs, ga.w, ba.w));
        row4[lane + 32] = make_float4(fmaf(xb.x * rs, gb.x, bb.x), fmaf(xb.y * rs, gb.y, bb.y),
                                      fmaf(xb.z * rs, gb.z, bb.z), fmaf(xb.w * rs, gb.w, bb.w));
    }
}

extern "C" void kernel_launch(void* const* d_in, const int* in_sizes, int n_in,
                              void* d_out, int out_size) {
    (void)in_sizes; (void)n_in; (void)out_size;
    const float* feats  = (const float*)d_in[0];
    const float* proj_w = (const float*)d_in[1];
    const float* proj_b = (const float*)d_in[2];
    const float* wq     = (const float*)d_in[3];
    const float* wk     = (const float*)d_in[4];
    const float* wv     = (const float*)d_in[5];
    const float* bq     = (const float*)d_in[6];
    const float* bk     = (const float*)d_in[7];
    const float* bv     = (const float*)d_in[8];
    const float* wo     = (const float*)d_in[9];
    const float* bo     = (const float*)d_in[10];
    const float* ng     = (const float*)d_in[11];
    const float* nb     = (const float*)d_in[12];
    const float* tfw    = (const float*)d_in[13];
    const float* fg     = (const float*)d_in[14];
    const float* fb     = (const float*)d_in[15];
    float* out = (float*)d_out;

    size_t smem = SMEM_FLOATS * sizeof(float);
    cudaFuncSetAttribute(cma_fused, cudaFuncAttributeMaxDynamicSharedMemorySize, (int)smem);
    cma_fused<<<NBLK, THREADS, smem>>>(feats, proj_w, proj_b, wq, wk, wv, bq, bk, bv,
                                       wo, bo, ng, nb, tfw, fg, fb, out);
}

// round 4
// speedup vs baseline: 2.3886x; 2.3886x over previous
#include <cuda_runtime.h>

#define EPSF 1e-5f

namespace {
constexpr int NBLK = 1024;
constexpr int THREADS = 256;
constexpr int CTXP = 68;           // all GEMM pitches = 68: frag loads conflict-free (pitch%32==4)
constexpr int WP   = 68;
constexpr int RP   = 68;
constexpr int BP   = 68;
constexpr int PC1  = 132;          // phase-1 pitch (k=128), 132%32==4
constexpr int HS   = 64 * RP + 4;

constexpr int OFF_CTX = 0;                      // 256*68 = 17408
constexpr int OFF_W   = OFF_CTX + 256 * CTXP;   // 4*64*68 = 17408
constexpr int OFF_A   = OFF_W + 4 * 64 * WP;    // 17424
constexpr int OFF_B   = OFF_A + 4 * HS;         // 4352
constexpr int OFF_AB  = OFF_B + 64 * BP;        // 1024
constexpr int SMEM_FLOATS = OFF_AB + 1024;      // 57616 floats = 230464 B
}

__device__ __forceinline__ float warp_sum(float v) {
#pragma unroll
    for (int o = 16; o; o >>= 1) v += __shfl_xor_sync(0xffffffffu, v, o);
    return v;
}
__device__ __forceinline__ unsigned cvt_tf32(float x) {
    unsigned u; asm("cvt.rna.tf32.f32 %0, %1;" : "=r"(u) : "f"(x)); return u;
}
__device__ __forceinline__ float cvtf(float x) { return __uint_as_float(cvt_tf32(x)); }
__device__ __forceinline__ void mma8(float4& c, unsigned a0, unsigned a1, unsigned a2, unsigned a3,
                                     unsigned b0, unsigned b1) {
    asm volatile("mma.sync.aligned.m16n8k8.row.col.f32.tf32.tf32.f32 "
                 "{%0,%1,%2,%3}, {%4,%5,%6,%7}, {%8,%9}, {%0,%1,%2,%3};\n"
                 : "+f"(c.x), "+f"(c.y), "+f"(c.z), "+f"(c.w)
                 : "r"(a0), "r"(a1), "r"(a2), "r"(a3), "r"(b0), "r"(b1));
}
__device__ __forceinline__ unsigned uu(const float* p) { return __float_as_uint(*p); }
__device__ __forceinline__ float dot4(float4 a, float4 b) {
    return fmaf(a.x, b.x, fmaf(a.y, b.y, fmaf(a.z, b.z, a.w * b.w)));
}
__device__ __forceinline__ void fma4(float4& a, float s, float4 w) {
    a.x = fmaf(s, w.x, a.x); a.y = fmaf(s, w.y, a.y);
    a.z = fmaf(s, w.z, a.z); a.w = fmaf(s, w.w, a.w);
}
__device__ __forceinline__ const float4* f4p(const float* p) {
    return reinterpret_cast<const float4*>(p);
}

__global__ __launch_bounds__(THREADS, 1)
void cma_fused(const float* __restrict__ feats, const float* __restrict__ proj_w,
               const float* __restrict__ proj_b, const float* __restrict__ wq,
               const float* __restrict__ wk, const float* __restrict__ wv,
               const float* __restrict__ bq, const float* __restrict__ bk,
               const float* __restrict__ bv, const float* __restrict__ wo,
               const float* __restrict__ bo, const float* __restrict__ ng,
               const float* __restrict__ nb, const float* __restrict__ tfw,
               const float* __restrict__ fg, const float* __restrict__ fb,
               float* __restrict__ out)
{
    (void)bk;  // cancels in the k'-softmax

    extern __shared__ float sm[];
    float* sctx = sm + OFF_CTX;
    float* swgt = sm + OFF_W;
    float* bufA = sm + OFF_A;
    float* bufB = sm + OFF_B;
    float* abuf = sm + OFF_AB;

    const int b    = blockIdx.x;
    const int tid  = threadIdx.x;
    const int lane = tid & 31;
    const int wid  = tid >> 5;
    const int lr   = lane >> 2;   // 0..7
    const int lc   = lane & 3;    // 0..3
    const int tr   = tid >> 4;    // scalar-phase tiling
    const int tc   = tid & 15;
    const int r0s  = tr * 4;
    const int c0s  = tc * 4;

    float wgt[4];
    {
        float t0 = __ldg(tfw + 0), t1 = __ldg(tfw + 1), t2 = __ldg(tfw + 2), t3 = __ldg(tfw + 3);
        float tm = fmaxf(fmaxf(t0, t1), fmaxf(t2, t3));
        float e0 = __expf(t0 - tm), e1 = __expf(t1 - tm), e2 = __expf(t2 - tm), e3 = __expf(t3 - tm);
        float inv = 1.f / (e0 + e1 + e2 + e3);
        wgt[0] = e0 * inv; wgt[1] = e1 * inv; wgt[2] = e2 * inv; wgt[3] = e3 * inv;
    }

    // ================= Phase 1 (tensor): proj -> sctx[(k*64+d)][t], tf32-rounded =================
    {
        float* spw = bufA;            // A: [d][c] pitch 132
        float* sfT = bufA + 64 * PC1; // B: [t][c] pitch 132 (feats transposed)
        for (int k = 0; k < 4; k++) {
            const float* fgl = feats + (size_t)(k * NBLK + b) * 8192;
            const float* pwg = proj_w + k * 8192;
#pragma unroll
            for (int idx = tid; idx < 8192; idx += THREADS) {
                int c = idx >> 6, t = idx & 63;
                sfT[t * PC1 + c] = cvtf(fgl[idx]);
            }
#pragma unroll
            for (int idx = tid; idx < 8192; idx += THREADS) {
                int d = idx >> 7, c = idx & 127;
                spw[d * PC1 + c] = cvtf(pwg[idx]);
            }
            __syncthreads();

            const int m0 = 16 * (wid & 3);
            const int n0 = 32 * (wid >> 2);
            float4 acc[4] = {{0,0,0,0},{0,0,0,0},{0,0,0,0},{0,0,0,0}};
            const float* arow = spw + (m0 + lr) * PC1 + lc;
#pragma unroll 4
            for (int k0 = 0; k0 < 128; k0 += 8) {
                unsigned a0 = uu(arow + k0),           a1 = uu(arow + 8 * PC1 + k0);
                unsigned a2 = uu(arow + k0 + 4),       a3 = uu(arow + 8 * PC1 + k0 + 4);
#pragma unroll
                for (int j = 0; j < 4; j++) {
                    const float* bp = sfT + (n0 + 8 * j + lr) * PC1 + k0 + lc;
                    mma8(acc[j], a0, a1, a2, a3, uu(bp), uu(bp + 4));
                }
            }
            float pb0 = __ldg(proj_b + k * 64 + m0 + lr);
            float pb1 = __ldg(proj_b + k * 64 + m0 + lr + 8);
            float* crow0 = sctx + (k * 64 + m0 + lr) * CTXP;
            float* crow1 = crow0 + 8 * CTXP;
#pragma unroll
            for (int j = 0; j < 4; j++) {
                int col = n0 + 8 * j + 2 * lc;
                crow0[col]     = cvtf(acc[j].x + pb0);
                crow0[col + 1] = cvtf(acc[j].y + pb0);
                crow1[col]     = cvtf(acc[j].z + pb1);
                crow1[col + 1] = cvtf(acc[j].w + pb1);
            }
            __syncthreads();
        }
    }

    // ================= Phase 2: per-model attention =================
    for (int i = 0; i < 4; i++) {
        float* swq_ = swgt;                 // [e'][t] direct
        float* swkT = swgt + 64 * WP;       // [t][e'] transposed
        float* swv_ = swgt + 2 * 64 * WP;   // [e][t]  direct
        float* swo_ = swgt + 3 * 64 * WP;   // [e'][e] direct
        {
            const float* gq = wq + i * 4096; const float* gk = wk + i * 4096;
            const float* gv = wv + i * 4096; const float* go = wo + i * 4096;
#pragma unroll
            for (int idx = tid; idx < 4096; idx += THREADS) {
                int e = idx >> 6, t = idx & 63;
                swq_[e * WP + t] = cvtf(gq[idx]);
                swkT[t * WP + e] = cvtf(gk[idx]);
                swv_[e * WP + t] = cvtf(gv[idx]);
                swo_[e * WP + t] = cvtf(go[idx]);
            }
        }
        __syncthreads();

        // ---- G1 (tensor): QP[r][e'] = bq + q_in[r] @ wq^T -> bufB ----
        {
            const int m0 = 16 * (wid & 3);
            const int n0 = 32 * (wid >> 2);
            int ra = m0 + lr, rb = ra + 8;
            int ja = ((ra >> 4) << 6) + ((ra & 15) << 2) + i;
            int jb = ((rb >> 4) << 6) + ((rb & 15) << 2) + i;
            const float* arow0 = sctx + ja * CTXP + lc;
            const float* arow1 = sctx + jb * CTXP + lc;
            float4 acc[4] = {{0,0,0,0},{0,0,0,0},{0,0,0,0},{0,0,0,0}};
#pragma unroll
            for (int k0 = 0; k0 < 64; k0 += 8) {
                unsigned a0 = uu(arow0 + k0), a1 = uu(arow1 + k0);
                unsigned a2 = uu(arow0 + k0 + 4), a3 = uu(arow1 + k0 + 4);
#pragma unroll
                for (int j = 0; j < 4; j++) {
                    const float* bp = swq_ + (n0 + 8 * j + lr) * WP + k0 + lc;
                    mma8(acc[j], a0, a1, a2, a3, uu(bp), uu(bp + 4));
                }
            }
            float* crow0 = bufB + (m0 + lr) * BP;
            float* crow1 = crow0 + 8 * BP;
#pragma unroll
            for (int j = 0; j < 4; j++) {
                int col = n0 + 8 * j + 2 * lc;
                float b0 = __ldg(bq + i * 64 + col), b1 = __ldg(bq + i * 64 + col + 1);
                crow0[col]     = cvtf(acc[j].x + b0);
                crow0[col + 1] = cvtf(acc[j].y + b1);
                crow1[col]     = cvtf(acc[j].z + b0);
                crow1[col + 1] = cvtf(acc[j].w + b1);
            }
        }
        __syncthreads();

        // ---- G2 (tensor): QK[h][r][t] = 0.25 * QP[:,head h] @ wk[head h,:]  -> bufA ----
        {
            const int h  = wid >> 1;
            const int n0 = 32 * (wid & 1);
#pragma unroll
            for (int mt = 0; mt < 4; mt++) {
                const int m0 = 16 * mt;
                const float* arow = bufB + (m0 + lr) * BP + 16 * h + lc;
                float4 acc[4] = {{0,0,0,0},{0,0,0,0},{0,0,0,0},{0,0,0,0}};
#pragma unroll
                for (int k0 = 0; k0 < 16; k0 += 8) {
                    unsigned a0 = uu(arow + k0),     a1 = uu(arow + 8 * BP + k0);
                    unsigned a2 = uu(arow + k0 + 4), a3 = uu(arow + 8 * BP + k0 + 4);
#pragma unroll
                    for (int j = 0; j < 4; j++) {
                        const float* bp = swkT + (n0 + 8 * j + lr) * WP + 16 * h + k0 + lc;
                        mma8(acc[j], a0, a1, a2, a3, uu(bp), uu(bp + 4));
                    }
                }
                float* crow0 = bufA + h * HS + (m0 + lr) * RP;
                float* crow1 = crow0 + 8 * RP;
#pragma unroll
                for (int j = 0; j < 4; j++) {
                    int col = n0 + 8 * j + 2 * lc;
                    crow0[col]     = cvtf(acc[j].x * 0.25f);
                    crow0[col + 1] = cvtf(acc[j].y * 0.25f);
                    crow1[col]     = cvtf(acc[j].z * 0.25f);
                    crow1[col + 1] = cvtf(acc[j].w * 0.25f);
                }
            }
        }
        __syncthreads();

        // ---- G3a (scalar): scores + softmax over k' -> abuf ----
#pragma unroll
        for (int p = 0; p < 4; p++) {
            int r   = wid * 8 + p * 2 + (lane >> 4);
            int sub = lane & 15;
            int h   = sub >> 2, kp = sub & 3;
            int j   = ((r >> 4) << 6) + ((r & 15) << 2) + kp;
            const float* qr = bufA + h * HS + r * RP;
            const float* cr = sctx + j * CTXP;
            float s = 0.f;
#pragma unroll
            for (int t0 = 0; t0 < 64; t0 += 4) s += dot4(*f4p(qr + t0), *f4p(cr + t0));
            float m = fmaxf(s, __shfl_xor_sync(0xffffffffu, s, 1));
            m = fmaxf(m, __shfl_xor_sync(0xffffffffu, m, 2));
            float pe  = __expf(s - m);
            float den = pe + __shfl_xor_sync(0xffffffffu, pe, 1);
            den += __shfl_xor_sync(0xffffffffu, den, 2);
            abuf[r * 16 + sub] = pe / den;
        }
        __syncthreads();

        // ---- G3b (scalar): AGG[h][r][t] = sum_kp a * ctx  (overwrites QK in bufA) ----
        {
            int jb_[4];
#pragma unroll
            for (int rr = 0; rr < 4; rr++) {
                int r = r0s + rr;
                jb_[rr] = ((r >> 4) << 6) + ((r & 15) << 2);
            }
#pragma unroll
            for (int h = 0; h < 4; h++) {
                float4 acc[4] = {{0,0,0,0},{0,0,0,0},{0,0,0,0},{0,0,0,0}};
#pragma unroll
                for (int rr = 0; rr < 4; rr++) {
                    float4 a4 = *f4p(abuf + (r0s + rr) * 16 + h * 4);
                    fma4(acc[rr], a4.x, *f4p(sctx + (jb_[rr] + 0) * CTXP + c0s));
                    fma4(acc[rr], a4.y, *f4p(sctx + (jb_[rr] + 1) * CTXP + c0s));
                    fma4(acc[rr], a4.z, *f4p(sctx + (jb_[rr] + 2) * CTXP + c0s));
                    fma4(acc[rr], a4.w, *f4p(sctx + (jb_[rr] + 3) * CTXP + c0s));
                }
#pragma unroll
                for (int rr = 0; rr < 4; rr++) {
                    float* dst = bufA + h * HS + (r0s + rr) * RP + c0s;
                    dst[0] = cvtf(acc[rr].x); dst[1] = cvtf(acc[rr].y);
                    dst[2] = cvtf(acc[rr].z); dst[3] = cvtf(acc[rr].w);
                }
            }
        }
        __syncthreads();

        // ---- G4 (tensor): OA[r][e] = bv + AGG[h(e)] @ wv[e-rows]^T -> bufB ----
        {
            const int h  = wid >> 1;
            const int mh = wid & 1;
#pragma unroll
            for (int mt = 0; mt < 2; mt++) {
                const int m0 = 32 * mh + 16 * mt;
                const float* arow = bufA + h * HS + (m0 + lr) * RP + lc;
                float4 acc[2] = {{0,0,0,0},{0,0,0,0}};
#pragma unroll
                for (int k0 = 0; k0 < 64; k0 += 8) {
                    unsigned a0 = uu(arow + k0),     a1 = uu(arow + 8 * RP + k0);
                    unsigned a2 = uu(arow + k0 + 4), a3 = uu(arow + 8 * RP + k0 + 4);
#pragma unroll
                    for (int j = 0; j < 2; j++) {
                        const float* bp = swv_ + (16 * h + 8 * j + lr) * WP + k0 + lc;
                        mma8(acc[j], a0, a1, a2, a3, uu(bp), uu(bp + 4));
                    }
                }
                float* crow0 = bufB + (m0 + lr) * BP;
                float* crow1 = crow0 + 8 * BP;
#pragma unroll
                for (int j = 0; j < 2; j++) {
                    int col = 16 * h + 8 * j + 2 * lc;
                    float b0 = __ldg(bv + i * 64 + col), b1 = __ldg(bv + i * 64 + col + 1);
                    crow0[col]     = cvtf(acc[j].x + b0);
                    crow0[col + 1] = cvtf(acc[j].y + b1);
                    crow1[col]     = cvtf(acc[j].z + b0);
                    crow1[col + 1] = cvtf(acc[j].w + b1);
                }
            }
        }
        __syncthreads();

        // ---- G5 (tensor): O[r][e'] = bo + OA @ wo^T -> bufA (full fp32, feeds LN) ----
        {
            const int m0 = 16 * (wid & 3);
            const int n0 = 32 * (wid >> 2);
            const float* arow = bufB + (m0 + lr) * BP + lc;
            float4 acc[4] = {{0,0,0,0},{0,0,0,0},{0,0,0,0},{0,0,0,0}};
#pragma unroll
            for (int k0 = 0; k0 < 64; k0 += 8) {
                unsigned a0 = uu(arow + k0),     a1 = uu(arow + 8 * BP + k0);
                unsigned a2 = uu(arow + k0 + 4), a3 = uu(arow + 8 * BP + k0 + 4);
#pragma unroll
                for (int j = 0; j < 4; j++) {
                    const float* bp = swo_ + (n0 + 8 * j + lr) * WP + k0 + lc;
                    mma8(acc[j], a0, a1, a2, a3, uu(bp), uu(bp + 4));
                }
            }
            float* crow0 = bufA + (m0 + lr) * RP;
            float* crow1 = crow0 + 8 * RP;
#pragma unroll
            for (int j = 0; j < 4; j++) {
                int col = n0 + 8 * j + 2 * lc;
                float b0 = __ldg(bo + i * 64 + col), b1 = __ldg(bo + i * 64 + col + 1);
                crow0[col]     = acc[j].x + b0;
                crow0[col + 1] = acc[j].y + b1;
                crow1[col]     = acc[j].z + b0;
                crow1[col + 1] = acc[j].w + b1;
            }
        }
        __syncthreads();

        // ---- LN over 64 (+residual q_in), scale by wgt[i], stage into out ----
#pragma unroll
        for (int p = 0; p < 8; p++) {
            int r   = wid * 8 + p;
            int jqr = ((r >> 4) << 6) + ((r & 15) << 2) + i;
            float x0 = bufA[r * RP + lane]      + sctx[jqr * CTXP + lane];
            float x1 = bufA[r * RP + lane + 32] + sctx[jqr * CTXP + lane + 32];
            float mean = warp_sum(x0 + x1) * (1.f / 64.f);
            float d0 = x0 - mean, d1 = x1 - mean;
            float var = warp_sum(d0 * d0 + d1 * d1) * (1.f / 64.f);
            float rs = rsqrtf(var + EPSF);
            float* dst = out + ((size_t)b * 16384 + r * 256 + i * 64);
            dst[lane]      = (d0 * rs * __ldg(ng + i * 64 + lane)      + __ldg(nb + i * 64 + lane))      * wgt[i];
            dst[lane + 32] = (d1 * rs * __ldg(ng + i * 64 + lane + 32) + __ldg(nb + i * 64 + lane + 32)) * wgt[i];
        }
        __syncthreads();
    }

    // ================= Phase 3: final LN over 256, in-place on out =================
    const float4* fg4 = f4p(fg);
    const float4* fb4 = f4p(fb);
#pragma unroll
    for (int p = 0; p < 8; p++) {
        int r = wid * 8 + p;
        float4* row4 = reinterpret_cast<float4*>(out + (size_t)b * 16384 + r * 256);
        float4 xa = row4[lane], xb = row4[lane + 32];
        float s = xa.x + xa.y + xa.z + xa.w + xb.x + xb.y + xb.z + xb.w;
        float mean = warp_sum(s) * (1.f / 256.f);
        xa.x -= mean; xa.y -= mean; xa.z -= mean; xa.w -= mean;
        xb.x -= mean; xb.y -= mean; xb.z -= mean; xb.w -= mean;
        float v = xa.x*xa.x + xa.y*xa.y + xa.z*xa.z + xa.w*xa.w
                + xb.x*xb.x + xb.y*xb.y + xb.z*xb.z + xb.w*xb.w;
        float var = warp_sum(v) * (1.f / 256.f);
        float rs = rsqrtf(var + EPSF);
        float4 ga = fg4[lane], gb = fg4[lane + 32];
        float4 ba = fb4[lane], bb = fb4[lane + 32];
        row4[lane]      = make_float4(fmaf(xa.x * rs, ga.x, ba.x), fmaf(xa.y * rs, ga.y, ba.y),
                                      fmaf(xa.z * rs, ga.z, ba.z), fmaf(xa.w * rs, ga.w, ba.w));
        row4[lane + 32] = make_float4(fmaf(xb.x * rs, gb.x, bb.x), fmaf(xb.y * rs, gb.y, bb.y),
                                      fmaf(xb.z * rs, gb.z, bb.z), fmaf(xb.w * rs, gb.w, bb.w));
    }
}

extern "C" void kernel_launch(void* const* d_in, const int* in_sizes, int n_in,
                              void* d_out, int out_size) {
    (void)in_sizes; (void)n_in; (void)out_size;
    const float* feats  = (const float*)d_in[0];
    const float* proj_w = (const float*)d_in[1];
    const float* proj_b = (const float*)d_in[2];
    const float* wq     = (const float*)d_in[3];
    const float* wk     = (const float*)d_in[4];
    const float* wv     = (const float*)d_in[5];
    const float* bq     = (const float*)d_in[6];
    const float* bk     = (const float*)d_in[7];
    const float* bv     = (const float*)d_in[8];
    const float* wo     = (const float*)d_in[9];
    const float* bo     = (const float*)d_in[10];
    const float* ng     = (const float*)d_in[11];
    const float* nb     = (const float*)d_in[12];
    const float* tfw    = (const float*)d_in[13];
    const float* fg     = (const float*)d_in[14];
    const float* fb     = (const float*)d_in[15];
    float* out = (float*)d_out;

    size_t smem = SMEM_FLOATS * sizeof(float);
    cudaFuncSetAttribute(cma_fused, cudaFuncAttributeMaxDynamicSharedMemorySize, (int)smem);
    cma_fused<<<NBLK, THREADS, smem>>>(feats, proj_w, proj_b, wq, wk, wv, bq, bk, bv,
                                       wo, bo, ng, nb, tfw, fg, fb, out);
}